// round 1
// baseline (speedup 1.0000x reference)
#include <cuda_runtime.h>

#define HW    4096
#define CCH   64
#define NPAIR 28
#define PP    441

// Scratch (device globals: allocation-free per harness rules)
__device__ __align__(16) float g_cor[(size_t)NPAIR * PP * HW];  // ~202 MB
__device__ float g_mean[PP];
__device__ float g_rstd[PP];
__device__ __align__(16) float g_w2t[PP * 64];  // folded weights, [p][o]
__device__ float g_bias[64];

// Bank-conflict swizzle: fold word-index bit5 into bit1 (float2-safe, involution)
__device__ __forceinline__ int swz(int b) { return b ^ ((b >> 4) & 2); }

// ---------------------------------------------------------------------------
// Correlation inner body: 4 contiguous w x NQ contiguous q register tile.
// f2 smem index = w + 2q  (width pre-padded by 20 on each side, row width 104)
// ---------------------------------------------------------------------------
template <int NQ>
__device__ __forceinline__ void corr_body(const float* __restrict__ f1row,
                                          const float* __restrict__ f2row,
                                          int a0, int a1, const int* boff,
                                          float (&acc)[6][4]) {
#pragma unroll 8
    for (int c = 0; c < 64; ++c) {
        const float* F1 = f1row + c * 64;
        const float* F2 = f2row + c * 104;
        float2 x = *reinterpret_cast<const float2*>(F1 + a0);
        float2 y = *reinterpret_cast<const float2*>(F1 + a1);
        float a[4] = {x.x, x.y, y.x, y.y};
        float bb[2 * (NQ + 1)];
#pragma unroll
        for (int m = 0; m < NQ + 1; ++m) {
            float2 v = *reinterpret_cast<const float2*>(F2 + boff[m]);
            bb[2 * m]     = v.x;
            bb[2 * m + 1] = v.y;
        }
#pragma unroll
        for (int j = 0; j < NQ; ++j)
#pragma unroll
            for (int k = 0; k < 4; ++k)
                acc[j][k] = fmaf(a[k], bb[k + 2 * j], acc[j][k]);
    }
}

// ---------------------------------------------------------------------------
// Kernel 1: correlation volume. grid (32 h-pairs, 28 pairs), 128 threads.
// smem: f1 [2][64][64] + f2 padded row [2][64][104]  = 84 KB dynamic
// cor[n, p*21+q, h, w] = sum_c f1[c,h,w] * f2[c, h+2p-20, w+2q-20]
// ---------------------------------------------------------------------------
__global__ void __launch_bounds__(128) corr_kernel(const float* __restrict__ feats) {
    extern __shared__ float sm[];
    float* f1s = sm;                  // [2][64][64]
    float* f2s = sm + 2 * 64 * 64;    // [2][64][104]

    const int tid = threadIdx.x;
    const int n   = blockIdx.y;
    const int h0  = blockIdx.x * 2;
    const int b   = n / 7, t = n % 7;
    const float* f1f = feats + (size_t)(b * 8 + t) * CCH * HW;
    const float* f2f = f1f + (size_t)CCH * HW;  // next frame, same batch

    // stage f1 rows (swizzled columns)
    for (int idx = tid; idx < 2 * 64 * 64; idx += 128) {
        int hh = idx >> 12;
        int c  = (idx >> 6) & 63;
        int w  = idx & 63;
        f1s[((hh << 6) + c) * 64 + swz(w)] = f1f[c * HW + (h0 + hh) * 64 + w];
    }

    const int hh = tid >> 6;
    const int r6 = tid & 63;
    const int qg = r6 >> 4;
    const int wg = r6 & 15;
    const int qbase = (qg == 0) ? 0 : 5 * qg + 1;  // q groups: 6,5,5,5
    const float* f1row = f1s + hh * (64 * 64);
    const float* f2row = f2s + hh * (64 * 104);
    const int a0 = swz(wg * 4);
    const int a1 = swz(wg * 4 + 2);
    int boff[7];
#pragma unroll
    for (int m = 0; m < 7; ++m) boff[m] = swz(wg * 4 + 2 * qbase + 2 * m);

    for (int p = 0; p < 21; ++p) {
        const int dy = 2 * p - 20;
        __syncthreads();
        // stage padded f2 rows for this dy (zeros outside the frame)
        for (int idx = tid; idx < 2 * 64 * 104; idx += 128) {
            int hhh = idx / (64 * 104);
            int rem = idx - hhh * (64 * 104);
            int c   = rem / 104;
            int wp  = rem - c * 104;
            int r   = h0 + hhh + dy;
            int ww  = wp - 20;
            float v = 0.f;
            if (((unsigned)r < 64u) & ((unsigned)ww < 64u))
                v = f2f[c * HW + r * 64 + ww];
            f2s[(hhh * 64 + c) * 104 + swz(wp)] = v;
        }
        __syncthreads();

        float acc[6][4];
#pragma unroll
        for (int j = 0; j < 6; ++j)
#pragma unroll
            for (int k = 0; k < 4; ++k) acc[j][k] = 0.f;

        if (qg == 0) corr_body<6>(f1row, f2row, a0, a1, boff, acc);
        else         corr_body<5>(f1row, f2row, a0, a1, boff, acc);

        const int nq = (qg == 0) ? 6 : 5;
        float* outp = g_cor + ((size_t)n * PP + (size_t)(p * 21 + qbase)) * HW
                      + (h0 + hh) * 64 + wg * 4;
        for (int j = 0; j < nq; ++j) {
            float4 v = make_float4(acc[j][0], acc[j][1], acc[j][2], acc[j][3]);
            *reinterpret_cast<float4*>(outp + (size_t)j * HW) = v;
        }
    }
}

// ---------------------------------------------------------------------------
// Kernel 2: per-channel batch stats (mean, rstd) over N,H,W.  441 blocks.
// ---------------------------------------------------------------------------
__global__ void __launch_bounds__(256) stats_kernel() {
    const int p   = blockIdx.x;
    const int tid = threadIdx.x;
    float s = 0.f, ss = 0.f;
    for (int n = 0; n < NPAIR; ++n) {
        const float4* row =
            reinterpret_cast<const float4*>(g_cor + ((size_t)n * PP + p) * HW);
        for (int i = tid; i < HW / 4; i += 256) {
            float4 v = row[i];
            s  += v.x + v.y + v.z + v.w;
            ss += v.x * v.x + v.y * v.y + v.z * v.z + v.w * v.w;
        }
    }
    __shared__ float rs[256], rss[256];
    rs[tid] = s; rss[tid] = ss;
    __syncthreads();
    for (int ofs = 128; ofs > 0; ofs >>= 1) {
        if (tid < ofs) { rs[tid] += rs[tid + ofs]; rss[tid] += rss[tid + ofs]; }
        __syncthreads();
    }
    if (tid == 0) {
        const float inv = 1.f / (float)(NPAIR * HW);
        float mean = rs[0] * inv;
        float var  = rss[0] * inv - mean * mean;
        g_mean[p] = mean;
        g_rstd[p] = rsqrtf(var + 1e-5f);
    }
}

// ---------------------------------------------------------------------------
// Kernel 3: fold BN into conv weights.  W2T[p][o] = conv_w[o,p]*gamma_p*rstd_p
//           bias[o] = sum_p conv_w[o,p]*(beta_p - gamma_p*rstd_p*mean_p)
// ---------------------------------------------------------------------------
__global__ void __launch_bounds__(256) fold_kernel(const float* __restrict__ gamma,
                                                   const float* __restrict__ beta,
                                                   const float* __restrict__ convw) {
    __shared__ float sscale[PP], sshift[PP];
    const int tid = threadIdx.x;
    for (int p = tid; p < PP; p += 256) {
        float sc = gamma[p] * g_rstd[p];
        sscale[p] = sc;
        sshift[p] = beta[p] - sc * g_mean[p];
    }
    __syncthreads();
    for (int idx = tid; idx < PP * 64; idx += 256) {
        int p = idx >> 6, o = idx & 63;
        g_w2t[idx] = convw[o * PP + p] * sscale[p];
    }
    if (tid < 64) {
        float bsum = 0.f;
        for (int p = 0; p < PP; ++p) bsum += convw[tid * PP + p] * sshift[p];
        g_bias[tid] = bsum;
    }
}

// ---------------------------------------------------------------------------
// Kernel 4: 1x1 conv as GEMM  [128 pix x 64 out] tile, K=441 in chunks of 21.
// grid (32 pixel-tiles, 28 pairs), 256 threads, 4pix x 8out register tile.
// ---------------------------------------------------------------------------
__global__ void __launch_bounds__(256) conv_kernel(float* __restrict__ out) {
    __shared__ float As[21 * 128];
    __shared__ float Bs[21 * 64];
    const int tid     = threadIdx.x;
    const int n       = blockIdx.y;
    const int pixbase = blockIdx.x * 128;
    const int og      = tid >> 5;   // 8 output-channel group
    const int pxg     = tid & 31;   // 4-pixel group
    const float* corn = g_cor + (size_t)n * PP * HW;

    float acc[8][4];
#pragma unroll
    for (int s = 0; s < 8; ++s)
#pragma unroll
        for (int r = 0; r < 4; ++r) acc[s][r] = 0.f;

    for (int pc = 0; pc < 21; ++pc) {
        __syncthreads();
        for (int idx = tid; idx < 21 * 128; idx += 256) {
            int i = idx >> 7, jx = idx & 127;
            As[idx] = corn[(size_t)(pc * 21 + i) * HW + pixbase + jx];
        }
        for (int idx = tid; idx < 21 * 64; idx += 256)
            Bs[idx] = g_w2t[pc * 21 * 64 + idx];
        __syncthreads();
#pragma unroll
        for (int i = 0; i < 21; ++i) {
            float4 a   = *reinterpret_cast<const float4*>(&As[i * 128 + pxg * 4]);
            float4 b03 = *reinterpret_cast<const float4*>(&Bs[i * 64 + og * 8]);
            float4 b47 = *reinterpret_cast<const float4*>(&Bs[i * 64 + og * 8 + 4]);
            float bv[8] = {b03.x, b03.y, b03.z, b03.w, b47.x, b47.y, b47.z, b47.w};
            float av[4] = {a.x, a.y, a.z, a.w};
#pragma unroll
            for (int s = 0; s < 8; ++s)
#pragma unroll
                for (int r = 0; r < 4; ++r)
                    acc[s][r] = fmaf(bv[s], av[r], acc[s][r]);
        }
    }

    const int b = n / 7, t = n % 7;
    float* outn = out + (size_t)(b * 8 + t) * 64 * HW + pixbase + pxg * 4;
#pragma unroll
    for (int s = 0; s < 8; ++s) {
        int o = og * 8 + s;
        float bo = g_bias[o];
        float4 v = make_float4(acc[s][0] + bo, acc[s][1] + bo,
                               acc[s][2] + bo, acc[s][3] + bo);
        *reinterpret_cast<float4*>(outn + (size_t)o * HW) = v;
    }
}

// ---------------------------------------------------------------------------
// Kernel 5: zero the appended time frame (t = 7) for all batches.
// ---------------------------------------------------------------------------
__global__ void zero_tail_kernel(float* __restrict__ out) {
    int idx = blockIdx.x * 256 + threadIdx.x;   // 4*64*4096/4 = 262144 float4
    if (idx < 262144) {
        int b = idx >> 16;
        int r = idx & 65535;
        reinterpret_cast<float4*>(out)[(size_t)(b * 8 + 7) * 64 * 1024 + r] =
            make_float4(0.f, 0.f, 0.f, 0.f);
    }
}

// ---------------------------------------------------------------------------
extern "C" void kernel_launch(void* const* d_in, const int* in_sizes, int n_in,
                              void* d_out, int out_size) {
    const float* feats = (const float*)d_in[0];
    const float* gamma = (const float*)d_in[1];
    const float* beta  = (const float*)d_in[2];
    const float* convw = (const float*)d_in[3];
    float* out = (float*)d_out;

    const int corr_smem = (2 * 64 * 64 + 2 * 64 * 104) * 4;  // 86016 B
    cudaFuncSetAttribute(corr_kernel, cudaFuncAttributeMaxDynamicSharedMemorySize,
                         corr_smem);

    corr_kernel<<<dim3(32, 28), 128, corr_smem>>>(feats);
    stats_kernel<<<441, 256>>>();
    fold_kernel<<<1, 256>>>(gamma, beta, convw);
    conv_kernel<<<dim3(32, 28), 256>>>(out);
    zero_tail_kernel<<<1024, 256>>>(out);
}